// round 17
// baseline (speedup 1.0000x reference)
#include <cuda_runtime.h>
#include <cuda_fp16.h>

#define B_     4
#define CIN    256
#define CO_    64
#define N_     576   // 24*24
#define CV_    256
#define SPLITS 4     // k-splits: chunk counts {5,5,4,4} of 32 k each (18 total)

// Scratch (device globals — no allocation allowed)
__device__ unsigned g_kph[B_ * N_ * 32];   // (B, Nk, 32) half2 pairs over c
__device__ unsigned g_qph[B_ * N_ * 32];   // (B, Nq, 32)
__device__ __half   g_vh[B_ * CV_ * N_];   // fp16 copy of value

// ---------- packed helpers ----------
__device__ __forceinline__ unsigned long long pack2(float lo, float hi) {
    unsigned long long r;
    asm("mov.b64 %0, {%1, %2};" : "=l"(r) : "f"(lo), "f"(hi));
    return r;
}
__device__ __forceinline__ void unpack2(unsigned long long v, float& lo, float& hi) {
    asm("mov.b64 {%0, %1}, %2;" : "=f"(lo), "=f"(hi) : "l"(v));
}
__device__ __forceinline__ unsigned long long ffma2(unsigned long long a,
                                                    unsigned long long b,
                                                    unsigned long long c) {
    unsigned long long d;
    asm("fma.rn.f32x2 %0, %1, %2, %3;" : "=l"(d) : "l"(a), "l"(b), "l"(c));
    return d;
}
__device__ __forceinline__ float tanhfast(float x) {
    float y;
    asm("tanh.approx.f32 %0, %1;" : "=f"(y) : "f"(x));
    return y;
}
__device__ __forceinline__ unsigned tanh_h2(unsigned x) {
    unsigned y;
    asm("tanh.approx.f16x2 %0, %1;" : "=r"(y) : "r"(x));
    return y;
}
__device__ __forceinline__ __half2 u2h(unsigned u) { return *(__half2*)&u; }
__device__ __forceinline__ unsigned h2u(__half2 h) { return *(unsigned*)&h; }
__device__ __forceinline__ unsigned su32(const void* p) {
    return (unsigned)__cvta_generic_to_shared(p);
}
__device__ __forceinline__ void cp16(unsigned dst, const void* src) {
    asm volatile("cp.async.cg.shared.global [%0], [%1], 16;" :: "r"(dst), "l"(src));
}
__device__ __forceinline__ void cp8(unsigned dst, const void* src) {
    asm volatile("cp.async.ca.shared.global [%0], [%1], 8;" :: "r"(dst), "l"(src));
}
__device__ __forceinline__ void cp_commit() {
    asm volatile("cp.async.commit_group;" ::: "memory");
}
__device__ __forceinline__ void cp_wait_all() {
    asm volatile("cp.async.wait_group 0;" ::: "memory");
}

// ============================================================================
// Kernel A: kind 0/1: projections -> half2 (+ kind-0 zero-inits d_out).
//           kind 2: convert V -> fp16 (g_vh).
// grid (18, B, 3), 512 thr, __launch_bounds__(512,1).  (unchanged)
// ============================================================================
#define PROJ_SMEM_BYTES ((256 * 32 + 256 * 66) * 4)

__global__ void __launch_bounds__(512, 1) proj_kernel(
    const float* __restrict__ key, const float* __restrict__ query,
    const float* __restrict__ value,
    const float* __restrict__ Wk,  const float* __restrict__ bk,
    const float* __restrict__ Wq,  const float* __restrict__ bq,
    float4* __restrict__ out_zero)
{
    const int kind = blockIdx.z;
    const int b  = blockIdx.y;
    const int n0 = blockIdx.x * 32;
    const int t  = threadIdx.x;

    if (kind == 2) {   // ---- V -> fp16 ----
        #pragma unroll
        for (int i = 0; i < 16; i++) {
            const int idx = i * 512 + t;          // 0..8191 = 256c x 32n
            const int c = idx >> 5;
            const int n = n0 + (idx & 31);
            g_vh[((size_t)(b * CV_ + c)) * N_ + n] =
                __float2half_rn(value[((size_t)(b * CV_ + c)) * N_ + n]);
        }
        return;
    }

    extern __shared__ float smem[];
    float (*sX)[32] = (float (*)[32])smem;               // [256 ch][32 n]
    float (*sW)[66] = (float (*)[66])(smem + 256 * 32);  // [256 ch][64 c]

    const float* X    = kind ? query : key;    // (B, CIN, N)
    const float* W    = kind ? Wq    : Wk;     // (CO, CIN)
    const float* bias = kind ? bq    : bk;
    unsigned* outp    = kind ? g_qph : g_kph;  // (B, N, 32) half2

    // ---- zero d_out (kind-0 blocks; 72 blocks x 512 thr x 4 float4) ----
    if (kind == 0) {
        const int idx = (b * 18 + blockIdx.x) * 512 + t;   // 0..36863
        #pragma unroll
        for (int i = 0; i < 4; i++)
            out_zero[i * 36864 + idx] = make_float4(0.f, 0.f, 0.f, 0.f);
    }

    {   // stage X: 256ch x 32n as float4 (coalesced)
        const int n4  = (t & 7) * 4;
        const int chb = t >> 3;                  // 0..63
        #pragma unroll
        for (int i = 0; i < 4; i++) {
            const int ch = chb + i * 64;
            *(float4*)&sX[ch][n4] =
                *(const float4*)&X[((size_t)(b * CIN + ch)) * N_ + n0 + n4];
        }
    }
    {   // stage W transposed: sW[ch][c]
        const int ch = t & 255;
        const int cb = (t >> 8) * 32;            // 0 or 32
        #pragma unroll 8
        for (int j = 0; j < 32; j++) {
            const int cr = cb + j;
            sW[ch][cr] = W[cr * CIN + ch];
        }
    }
    __syncthreads();

    const int ng = t & 15;           // n = 2*ng, 2*ng+1
    const int c  = (t >> 4) * 2;     // c, c+1

    unsigned long long a0 = 0ull, a1 = 0ull;

    for (int ch0 = 0; ch0 < CIN; ch0 += 8) {
        unsigned long long xps[8];
        float2 ws[8];
        #pragma unroll
        for (int i = 0; i < 8; i++) {
            xps[i] = *(const unsigned long long*)&sX[ch0 + i][ng * 2];
            ws[i]  = *(const float2*)&sW[ch0 + i][c];
        }
        #pragma unroll
        for (int i = 0; i < 8; i++) {
            a0 = ffma2(xps[i], pack2(ws[i].x, ws[i].x), a0);
            a1 = ffma2(xps[i], pack2(ws[i].y, ws[i].y), a1);
        }
    }

    const float bv0 = bias[c];
    const float bv1 = bias[c + 1];
    float c0n0, c0n1, c1n0, c1n1;
    unpack2(a0, c0n0, c0n1);
    unpack2(a1, c1n0, c1n1);

    const int n  = n0 + ng * 2;
    const int cc = c >> 1;
    outp[((size_t)b * N_ + n + 0) * 32 + cc] =
        h2u(__floats2half2_rn(c0n0 + bv0, c1n0 + bv1));
    outp[((size_t)b * N_ + n + 1) * 32 + cc] =
        h2u(__floats2half2_rn(c0n1 + bv0, c1n1 + bv1));
}

// ============================================================================
// Kernel B (FUSED v10, MUFU-fed pipeline): block = (32 q, split, b),
// grid (18, 4, 4) = 288, 256 thr, __launch_bounds__(256,2) -> 2 blocks/SM.
// Per chunk: [cp.wait (G(ch), issued last iter) ; ONE bar ; issue G(ch+1) ;
//            mma(ch-1) ; attn(ch)] — mma and attn are adjacent (no barrier
//            between), so warps keep MUFU fed during tensor/LDS stalls.
// Buffers: sVh/skh triple, sAh double. Lifetime audit:
//   V(ch+1)->sVh[(ch+1)%3]: old = chunk ch-2, last read by mma(ch-2) in iter
//     ch-1, separated by iter-ch bar.  k same.  attn(ch)->sAh[ch&1]: old
//     reader mma(ch-2) in iter ch-1, bar'd.  mma(ch-1) reads sAh[(ch-1)&1]
//     written iter ch-1, made visible by iter-ch bar.  cp visibility:
//     wait_group 0 BEFORE the bar -> all threads see G(ch).
// ============================================================================
__global__ void __launch_bounds__(256, 2) fused_kernel(
    const float* __restrict__ wf, const float* __restrict__ bfp,
    float* __restrict__ out)
{
    __shared__ unsigned sqh[32][34];                    // q tile half2 pairs
    __shared__ unsigned swh[32];
    __shared__ unsigned skh[3][32][34];                 // k chunk, triple-buf
    __shared__ __align__(16) __half sAh[2][32][40];     // attn fp16, double-buf
    __shared__ __align__(16) __half sVh[3][256][40];    // V fp16, triple-buf

    const int b  = blockIdx.z;
    const int q0 = blockIdx.x * 32;
    const int s  = blockIdx.y;
    const int cstart = s * 4 + (s < 2 ? s : 2);   // chunk starts 0,5,10,14
    const int ccount = (s < 2) ? 5 : 4;

    const int t  = threadIdx.x;
    const int lane = t & 31;
    const int w    = t >> 5;

    // ---- stage q tile (512 uint2) + wf (once) ----
    #pragma unroll
    for (int j = 0; j < 2; j++) {
        const int idx = t + j * 256;
        const int r = idx >> 4;              // 0..31
        const int u = (idx & 15) * 2;
        *(uint2*)&sqh[r][u] =
            *(const uint2*)&g_qph[((size_t)b * N_ + q0 + r) * 32 + u];
    }
    if (t < 32) {
        const float2 wv = *(const float2*)&wf[t * 2];
        swh[t] = h2u(__floats2half2_rn(wv.x, wv.y));
    }
    const float bf = __ldg(bfp);

    const __half*   vbase = g_vh  + (size_t)b * CV_ * N_;
    const unsigned* kpb   = g_kph + ((size_t)b * N_) * 32;

    // ---- prologue: issue G0 (chunk cstart) into buffers 0 ----
    {
        const int k0 = cstart * 32;
        #pragma unroll
        for (int i = 0; i < 4; i++) {
            const int idx = i * 256 + t;     // 0..1023 uint4
            const int c   = idx >> 2;
            const int kq  = (idx & 3) * 8;
            cp16(su32(&sVh[0][c][kq]), vbase + (size_t)c * N_ + k0 + kq);
        }
        #pragma unroll
        for (int i = 0; i < 2; i++) {
            const int idx = i * 256 + t;     // 0..511 (8B units)
            const int kk  = idx >> 4;
            const int u   = (idx & 15) * 2;
            cp8(su32(&skh[0][kk][u]), kpb + (size_t)(k0 + kk) * 32 + u);
        }
        cp_commit();
    }

    // attn mapping: scores (ka, qa + 8i), i = 0..3
    const int ka = lane;
    const int qa = w;                        // 0..7

    // mma accumulators: warp owns c = w*32..w*32+31 (2 c-tiles), 4 q-tiles
    float d[2][4][4];
    #pragma unroll
    for (int ct = 0; ct < 2; ct++)
        #pragma unroll
        for (int qt = 0; qt < 4; qt++)
            #pragma unroll
            for (int i = 0; i < 4; i++) d[ct][qt][i] = 0.f;

    for (int ch = 0; ch <= ccount; ch++) {
        cp_wait_all();       // G(ch) complete (this thread's copies)
        __syncthreads();     // all threads' G(ch) visible; prev iter done

        // ---- issue G(ch+1) (hidden across this iter's mma+attn) ----
        if (ch + 1 < ccount) {
            const int kg = (cstart + ch + 1) * 32;
            const int nb = (ch + 1) % 3;
            #pragma unroll
            for (int i = 0; i < 4; i++) {
                const int idx = i * 256 + t;
                const int c   = idx >> 2;
                const int kq  = (idx & 3) * 8;
                cp16(su32(&sVh[nb][c][kq]), vbase + (size_t)c * N_ + kg + kq);
            }
            #pragma unroll
            for (int i = 0; i < 2; i++) {
                const int idx = i * 256 + t;
                const int kk  = idx >> 4;
                const int u   = (idx & 15) * 2;
                cp8(su32(&skh[nb][kk][u]), kpb + (size_t)(kg + kk) * 32 + u);
            }
            cp_commit();
        }

        // ---- mma(ch-1): D += V[c,k] * A[k,q]  (adjacent with attn below) ----
        if (ch >= 1) {
            const int pb3 = (ch - 1) % 3;
            const int pA  = (ch - 1) & 1;
            #pragma unroll
            for (int ct = 0; ct < 2; ct++) {
                unsigned af[2][4];
                #pragma unroll
                for (int kt = 0; kt < 2; kt++) {
                    const unsigned addr = su32(
                        &sVh[pb3][w * 32 + ct * 16 + (lane & 15)]
                            [kt * 16 + (lane >> 4) * 8]);
                    asm volatile(
                        "ldmatrix.sync.aligned.m8n8.x4.shared.b16 {%0,%1,%2,%3}, [%4];"
                        : "=r"(af[kt][0]), "=r"(af[kt][1]),
                          "=r"(af[kt][2]), "=r"(af[kt][3]) : "r"(addr));
                }
                #pragma unroll
                for (int qt = 0; qt < 4; qt++) {
                    #pragma unroll
                    for (int kt = 0; kt < 2; kt++) {
                        unsigned b0, b1;
                        const unsigned addr =
                            su32(&sAh[pA][kt * 16 + (lane & 15)][qt * 8]);
                        asm volatile(
                            "ldmatrix.sync.aligned.m8n8.x2.trans.shared.b16 {%0,%1}, [%2];"
                            : "=r"(b0), "=r"(b1) : "r"(addr));
                        asm volatile(
                            "mma.sync.aligned.m16n8k16.row.col.f32.f16.f16.f32 "
                            "{%0,%1,%2,%3}, {%4,%5,%6,%7}, {%8,%9}, {%0,%1,%2,%3};"
                            : "+f"(d[ct][qt][0]), "+f"(d[ct][qt][1]),
                              "+f"(d[ct][qt][2]), "+f"(d[ct][qt][3])
                            : "r"(af[kt][0]), "r"(af[kt][1]),
                              "r"(af[kt][2]), "r"(af[kt][3]),
                              "r"(b0), "r"(b1));
                    }
                }
            }
        }

        // ---- attn(ch): 4 scores per thread -> sAh[ch&1] ----
        if (ch < ccount) {
            const int b3 = ch % 3;
            const int cA = ch & 1;
            __half2 ae[4], ao[4];
            #pragma unroll
            for (int i = 0; i < 4; i++) { ae[i] = __float2half2_rn(0.f); ao[i] = ae[i]; }
            const unsigned* __restrict__ krow = skh[b3][ka];
            #pragma unroll 8
            for (int cc = 0; cc < 32; cc += 2) {
                const uint2 kv = *(const uint2*)&krow[cc];
                const uint2 wv = *(const uint2*)&swh[cc];
                #pragma unroll
                for (int i = 0; i < 4; i++) {
                    const uint2 qv = *(const uint2*)&sqh[qa + 8 * i][cc];
                    const unsigned t0 = tanh_h2(h2u(__hadd2(u2h(kv.x), u2h(qv.x))));
                    const unsigned t1 = tanh_h2(h2u(__hadd2(u2h(kv.y), u2h(qv.y))));
                    ae[i] = __hfma2(u2h(t0), u2h(wv.x), ae[i]);
                    ao[i] = __hfma2(u2h(t1), u2h(wv.y), ao[i]);
                }
            }
            #pragma unroll
            for (int i = 0; i < 4; i++) {
                const float2 fe = __half22float2(ae[i]);
                const float2 fo = __half22float2(ao[i]);
                const float sv = bf + ((fe.x + fe.y) + (fo.x + fo.y));
                sAh[cA][ka][qa + 8 * i] =
                    __float2half_rn(fmaf(0.5f, tanhfast(0.5f * sv), 0.5f));
            }
        }
    }

    // ---- epilogue: atomicAdd k-partials (out zeroed by proj_kernel) ----
    const int gid = lane >> 2;       // D row within tile
    const int tig = lane & 3;        // D col pair
    #pragma unroll
    for (int ct = 0; ct < 2; ct++)
        #pragma unroll
        for (int qt = 0; qt < 4; qt++) {
            const int c_r = w * 32 + ct * 16 + gid;
            const int q_c = q0 + qt * 8 + tig * 2;
            float* op = out + ((size_t)(b * CV_ + c_r)) * N_ + q_c;
            atomicAdd(op,              d[ct][qt][0]);
            atomicAdd(op + 1,          d[ct][qt][1]);
            atomicAdd(op + 8 * N_,     d[ct][qt][2]);
            atomicAdd(op + 8 * N_ + 1, d[ct][qt][3]);
        }
}

// ============================================================================
extern "C" void kernel_launch(void* const* d_in, const int* in_sizes, int n_in,
                              void* d_out, int out_size)
{
    const float* key   = (const float*)d_in[0];
    const float* query = (const float*)d_in[1];
    const float* value = (const float*)d_in[2];
    const float* Wk    = (const float*)d_in[3];
    const float* bk    = (const float*)d_in[4];
    const float* Wq    = (const float*)d_in[5];
    const float* bq    = (const float*)d_in[6];
    const float* wf    = (const float*)d_in[7];
    const float* bf    = (const float*)d_in[8];
    float* out = (float*)d_out;

    static int attr_set = 0;
    if (!attr_set) {
        cudaFuncSetAttribute(proj_kernel,
                             cudaFuncAttributeMaxDynamicSharedMemorySize,
                             PROJ_SMEM_BYTES);
        attr_set = 1;
    }

    proj_kernel<<<dim3(N_ / 32, B_, 3), 512, PROJ_SMEM_BYTES>>>(
        key, query, value, Wk, bk, Wq, bq, (float4*)out);
    fused_kernel<<<dim3(N_ / 32, SPLITS, B_), 256>>>(wf, bf, out);
}